// round 14
// baseline (speedup 1.0000x reference)
#include <cuda_runtime.h>
#include <cuda_fp16.h>
#include <math.h>
#include <stdint.h>

// ---------------- problem constants ----------------
#define TOK   16384
#define DIM   1024
#define DFF   4096
#define NEXP  8
#define CAP   3277
#define TM    128
#define PADMAX (TOK + NEXP*TM)          // 17408
#define MAXROWTILES (PADMAX/TM)         // 136
#define KC    64                         // K chunk (fp16 elems)
#define STAGE 49152                      // A 16K + B 32K
#define NSTAGE 3
#define SMEM_REQ (NSTAGE*STAGE + 1024)   // 148480; 1 CTA/SM
#define NB_ROUT (TOK/8)                  // 2048 router blocks (8 warps = 8 tokens)
#define NB_CVT  2048                     // blocks per weight tensor (16 tiles each)

// ---------------- device scratch ----------------
__device__ unsigned char g_selmask[TOK];
__device__ signed char   g_final[TOK];
__device__ int g_off[NEXP + 1];
__device__ int g_perm[PADMAX];
__device__ __half g_Ag[(size_t)PADMAX * DIM];        // gathered x, fp16
__device__ __half g_H [(size_t)PADMAX * DFF];        // gelu intermediate, fp16
__device__ __half g_W1[(size_t)NEXP * DFF * DIM];    // W1^T fp16
__device__ __half g_W2[(size_t)NEXP * DIM * DFF];    // W2^T fp16

// ---------------- helpers ----------------
__device__ __forceinline__ uint32_t smem_u32(const void* p) {
    return (uint32_t)__cvta_generic_to_shared(p);
}
#define SWZ128(o) ((o) ^ (((o) >> 3) & 0x70))

#define CP16I(dst, src, DOF, SOF) \
    asm volatile("cp.async.cg.shared.global [%0+%2], [%1+%3], 16;" \
        :: "r"(dst), "l"(src), "n"(DOF), "n"(SOF) : "memory")
#define CP_COMMIT() asm volatile("cp.async.commit_group;" ::: "memory")
#define CP_WAIT1()  asm volatile("cp.async.wait_group 1;" ::: "memory")

__device__ __forceinline__ void ldsm4(uint32_t& r0, uint32_t& r1, uint32_t& r2,
                                      uint32_t& r3, uint32_t addr) {
    asm volatile("ldmatrix.sync.aligned.m8n8.x4.shared.b16 {%0,%1,%2,%3}, [%4];"
                 : "=r"(r0), "=r"(r1), "=r"(r2), "=r"(r3) : "r"(addr));
}

__device__ __forceinline__ void mma16816(float* c, const uint32_t* a,
                                         uint32_t b0, uint32_t b1) {
    asm volatile(
        "mma.sync.aligned.m16n8k16.row.col.f32.f16.f16.f32 "
        "{%0,%1,%2,%3}, {%4,%5,%6,%7}, {%8,%9}, {%0,%1,%2,%3};"
        : "+f"(c[0]), "+f"(c[1]), "+f"(c[2]), "+f"(c[3])
        : "r"(a[0]), "r"(a[1]), "r"(a[2]), "r"(a[3]), "r"(b0), "r"(b1));
}

__device__ __forceinline__ float gelu_exact(float v) {
    return 0.5f * v * (1.0f + erff(v * 0.70710678118654752f));
}

// transpose+convert one 32x32 tile (256 threads, 32x33 smem scratch)
__device__ __forceinline__ void cvt_tile(const float* __restrict__ s,
                                         __half* __restrict__ d,
                                         float* tsh, int R, int C,
                                         int r0, int c0, int tx, int ty)
{
#pragma unroll
    for (int i = 0; i < 4; i++)
        tsh[(ty + i * 8) * 33 + tx] = s[(size_t)(r0 + ty + i * 8) * C + c0 + tx];
    __syncthreads();
#pragma unroll
    for (int i = 0; i < 4; i++) {
        int orow = c0 + ty + i * 8;
        int ocol = r0 + tx;
        d[(size_t)orow * R + ocol] = __float2half(tsh[tx * 33 + ty + i * 8]);
    }
    __syncthreads();
}

// ---------------- prep: router + both weight conversions, one launch -------
__global__ __launch_bounds__(256) void prep_kernel(
    const float* __restrict__ x, const float* __restrict__ noise,
    const float* __restrict__ rw, const float* __restrict__ rb,
    const float* __restrict__ w1, __half* __restrict__ w1dst,
    const float* __restrict__ w2, __half* __restrict__ w2dst)
{
    __shared__ float sh[32 * 33];
    int bid = blockIdx.x;
    int tid = threadIdx.x;

    if (bid < NB_ROUT) {
        int wid = tid >> 5, lane = tid & 31;
        int t = bid * 8 + wid;
        const float4* xr4 = reinterpret_cast<const float4*>(x + (size_t)t * DIM);
        const float4* rw4 = reinterpret_cast<const float4*>(rw);
        float acc[NEXP];
#pragma unroll
        for (int e = 0; e < NEXP; e++) acc[e] = 0.f;
#pragma unroll
        for (int i = 0; i < 8; i++) {
            int idx = i * 32 + lane;
            float4 xv = xr4[idx];
#pragma unroll
            for (int e = 0; e < NEXP; e++) {
                float4 wv = rw4[e * 256 + idx];
                acc[e] += xv.x * wv.x + xv.y * wv.y + xv.z * wv.z + xv.w * wv.w;
            }
        }
#pragma unroll
        for (int o = 16; o > 0; o >>= 1)
#pragma unroll
            for (int e = 0; e < NEXP; e++)
                acc[e] += __shfl_xor_sync(0xFFFFFFFFu, acc[e], o);
        if (lane == 0) {
            float lg[NEXP];
#pragma unroll
            for (int e = 0; e < NEXP; e++)
                lg[e] = acc[e] + rb[e] + noise[t * NEXP + e] * 0.02f;
            int e1 = 0;
#pragma unroll
            for (int e = 1; e < NEXP; e++) if (lg[e] > lg[e1]) e1 = e;
            int e2 = -1;
#pragma unroll
            for (int e = 0; e < NEXP; e++) {
                if (e == e1) continue;
                if (e2 < 0 || lg[e] > lg[e2]) e2 = e;
            }
            g_selmask[t] = (unsigned char)((1 << e1) | (1 << e2));
        }
        return;
    }

    int tx = tid & 31, ty = tid >> 5;
    if (bid < NB_ROUT + NB_CVT) {
        int cb = bid - NB_ROUT;
#pragma unroll 1
        for (int it = 0; it < 16; it++) {
            int g = cb * 16 + it;
            int e = g >> 12;
            int rem = g & 4095;
            int tr = rem & 31;
            int tc = rem >> 5;
            cvt_tile(w1 + (size_t)e * DIM * DFF, w1dst + (size_t)e * DFF * DIM,
                     sh, DIM, DFF, tr * 32, tc * 32, tx, ty);
        }
        return;
    }
    int cb = bid - NB_ROUT - NB_CVT;
#pragma unroll 1
    for (int it = 0; it < 16; it++) {
        int g = cb * 16 + it;
        int e = g >> 12;
        int rem = g & 4095;
        int tr = rem & 127;
        int tc = rem >> 7;
        cvt_tile(w2 + (size_t)e * DFF * DIM, w2dst + (size_t)e * DIM * DFF,
                 sh, DFF, DIM, tr * 32, tc * 32, tx, ty);
    }
}

// ---------------- route: full routing resolution in one block --------------
__global__ __launch_bounds__(1024) void route_kernel()
{
    __shared__ uint64_t s0[1024], s1[1024];
    __shared__ int sF[NEXP], sOff[NEXP + 1];
    int tid = threadIdx.x;

    union { uint4 q; unsigned char b[16]; } u;
    u.q = reinterpret_cast<const uint4*>(g_selmask)[tid];
    uint32_t m[NEXP];
#pragma unroll
    for (int e = 0; e < NEXP; e++) m[e] = 0;
#pragma unroll
    for (int j = 0; j < 16; j++) {
        unsigned char sm = u.b[j];
#pragma unroll
        for (int e = 0; e < NEXP; e++)
            m[e] |= (uint32_t)((sm >> e) & 1) << j;
    }
    int cnt[NEXP];
#pragma unroll
    for (int e = 0; e < NEXP; e++) cnt[e] = __popc(m[e]);

    uint64_t p0 = (uint64_t)cnt[0] | ((uint64_t)cnt[1] << 16) |
                  ((uint64_t)cnt[2] << 32) | ((uint64_t)cnt[3] << 48);
    uint64_t p1 = (uint64_t)cnt[4] | ((uint64_t)cnt[5] << 16) |
                  ((uint64_t)cnt[6] << 32) | ((uint64_t)cnt[7] << 48);
    s0[tid] = p0; s1[tid] = p1;
    __syncthreads();
    for (int off = 1; off < 1024; off <<= 1) {
        uint64_t a0 = (tid >= off) ? s0[tid - off] : 0;
        uint64_t a1 = (tid >= off) ? s1[tid - off] : 0;
        __syncthreads();
        s0[tid] += a0; s1[tid] += a1;
        __syncthreads();
    }
    uint64_t i0 = s0[tid], i1 = s1[tid];
    int base[NEXP];
#pragma unroll
    for (int e = 0; e < 4; e++)
        base[e] = (int)((i0 >> (16 * e)) & 0xFFFF) - cnt[e];
#pragma unroll
    for (int e = 4; e < NEXP; e++)
        base[e] = (int)((i1 >> (16 * (e - 4))) & 0xFFFF) - cnt[e];

    union { int4 q; signed char c[16]; } fo;
    uint32_t fm[NEXP];
#pragma unroll
    for (int e = 0; e < NEXP; e++) fm[e] = 0;
#pragma unroll
    for (int j = 0; j < 16; j++) {
        int f = -1;
#pragma unroll
        for (int e = NEXP - 1; e >= 0; e--) {
            if ((m[e] >> j) & 1) {
                int rank = base[e] + __popc(m[e] & ((1u << j) - 1u));
                if (rank < CAP) { f = e; break; }
            }
        }
        fo.c[j] = (signed char)f;
        if (f >= 0) fm[f] |= 1u << j;
    }
    reinterpret_cast<int4*>(g_final)[tid] = fo.q;

    int fc[NEXP];
#pragma unroll
    for (int e = 0; e < NEXP; e++) fc[e] = __popc(fm[e]);
    uint64_t q0 = (uint64_t)fc[0] | ((uint64_t)fc[1] << 16) |
                  ((uint64_t)fc[2] << 32) | ((uint64_t)fc[3] << 48);
    uint64_t q1 = (uint64_t)fc[4] | ((uint64_t)fc[5] << 16) |
                  ((uint64_t)fc[6] << 32) | ((uint64_t)fc[7] << 48);
    __syncthreads();
    s0[tid] = q0; s1[tid] = q1;
    __syncthreads();
    for (int off = 1; off < 1024; off <<= 1) {
        uint64_t a0 = (tid >= off) ? s0[tid - off] : 0;
        uint64_t a1 = (tid >= off) ? s1[tid - off] : 0;
        __syncthreads();
        s0[tid] += a0; s1[tid] += a1;
        __syncthreads();
    }
    uint64_t j0 = s0[tid], j1 = s1[tid];
    int fbase[NEXP];
#pragma unroll
    for (int e = 0; e < 4; e++)
        fbase[e] = (int)((j0 >> (16 * e)) & 0xFFFF) - fc[e];
#pragma unroll
    for (int e = 4; e < NEXP; e++)
        fbase[e] = (int)((j1 >> (16 * (e - 4))) & 0xFFFF) - fc[e];

    if (tid == 1023) {
        int o = 0;
        sOff[0] = 0;
        for (int e = 0; e < NEXP; e++) {
            int F = (e < 4) ? (int)((j0 >> (16 * e)) & 0xFFFF)
                            : (int)((j1 >> (16 * (e - 4))) & 0xFFFF);
            sF[e] = F;
            o += ((F + TM - 1) / TM) * TM;
            sOff[e + 1] = o;
        }
    }
    __syncthreads();
    if (tid <= NEXP) g_off[tid] = sOff[tid];

#pragma unroll
    for (int j = 0; j < 16; j++) {
        int f = fo.c[j];
        if (f >= 0) {
            int pos = sOff[f] + fbase[f] + __popc(fm[f] & ((1u << j) - 1u));
            g_perm[pos] = tid * 16 + j;
        }
    }
    for (int e = 0; e < NEXP; e++)
        for (int i = sOff[e] + sF[e] + tid; i < sOff[e + 1]; i += 1024)
            g_perm[i] = TOK;
}

// fat gather: gather + zero-dropped
__global__ __launch_bounds__(256) void gather_kernel(
    const float* __restrict__ x, float* __restrict__ out)
{
    int bid = blockIdx.x;
    int tid = threadIdx.x;
    if (bid < PADMAX) {
        int tok = g_perm[bid];
        float4 v = make_float4(0.f, 0.f, 0.f, 0.f);
        if (tok < TOK)
            v = reinterpret_cast<const float4*>(x + (size_t)tok * DIM)[tid];
        __half h[4];
        h[0] = __float2half(v.x); h[1] = __float2half(v.y);
        h[2] = __float2half(v.z); h[3] = __float2half(v.w);
        reinterpret_cast<uint2*>(g_Ag + (size_t)bid * DIM)[tid] =
            *reinterpret_cast<uint2*>(h);
        return;
    }
    __shared__ int list[256];
    __shared__ int cnt;
    if (tid == 0) cnt = 0;
    __syncthreads();
    int t = (bid - PADMAX) * 256 + tid;
    if (g_final[t] < 0) { int p = atomicAdd(&cnt, 1); list[p] = t; }
    __syncthreads();
    float4 z = make_float4(0.f, 0.f, 0.f, 0.f);
    for (int i = 0; i < cnt; i++) {
        size_t row = (size_t)list[i] * DIM;
        reinterpret_cast<float4*>(out + row)[tid] = z;
    }
}

// ---------------- HMMA GEMM — 128m x 256n CTA tile, 64x64 warp tiles -------
// 8 warps (2m x 4n), acc 128 regs/thread; A tile 16KB + B tile 32KB per stage.
// Fragment smem traffic 4B/output (vs 6); 32-MMA ILP per 8-ldsm batch.
template<int KT, int NT, int MODE>
__global__ __launch_bounds__(256, 1) void gemm_kernel(
    const __half* __restrict__ A, const __half* __restrict__ B,
    const float* __restrict__ bias, float* __restrict__ out)
{
    int row0 = blockIdx.y * TM;
    if (row0 >= g_off[NEXP]) return;
    int e = 0;
#pragma unroll
    for (int i = 0; i < NEXP; i++) if (row0 >= g_off[i + 1]) e = i + 1;
    int n0 = blockIdx.x * 256;

    extern __shared__ __align__(1024) char smem_raw[];
    uint32_t sb = (smem_u32(smem_raw) + 1023) & ~1023u;

    int tid = threadIdx.x;
    int lane = tid & 31;
    int wid = tid >> 5;
    int wm = wid & 1;          // 2 m positions (64 rows each)
    int wn = wid >> 1;         // 4 n positions (64 cols each)
    int lrow = (lane & 7) + ((lane >> 3) & 1) * 8;
    int lkh2 = ((lane >> 4) * 8) * 2;

    constexpr int C = KT >> 6;

    // fill: A rows (tid>>3)+32j (j 0..3), B rows (tid>>3)+32j (j 0..7)
    uint32_t so = SWZ128(((tid >> 3) << 7) + ((tid & 7) << 4));
    const char* fA = (const char*)(A + (size_t)(row0 + (tid >> 3)) * KT
                                     + (tid & 7) * 8);
    const char* fB = (const char*)(B + ((size_t)e * NT + n0 + (tid >> 3)) * KT
                                     + (tid & 7) * 8);

    auto fill_stage = [&](uint32_t st, const char* a, const char* b) {
        uint32_t dA = st + so, dB = st + 16384 + so;
        CP16I(dA, a,     0, 0);
        CP16I(dA, a,  4096, 64 * KT);
        CP16I(dA, a,  8192, 128 * KT);
        CP16I(dA, a, 12288, 192 * KT);
        CP16I(dB, b,     0, 0);
        CP16I(dB, b,  4096, 64 * KT);
        CP16I(dB, b,  8192, 128 * KT);
        CP16I(dB, b, 12288, 192 * KT);
        CP16I(dB, b, 16384, 256 * KT);
        CP16I(dB, b, 20480, 320 * KT);
        CP16I(dB, b, 24576, 384 * KT);
        CP16I(dB, b, 28672, 448 * KT);
    };

    uint32_t arel[4], brel[4];
#pragma unroll
    for (int mt = 0; mt < 4; mt++)
        arel[mt] = SWZ128(((wm * 64 + mt * 16 + lrow) << 7) + lkh2);
#pragma unroll
    for (int nt = 0; nt < 4; nt++)
        brel[nt] = 16384u + SWZ128(((wn * 64 + nt * 16 + lrow) << 7) + lkh2);

    float acc[4][8][4];
#pragma unroll
    for (int mt = 0; mt < 4; mt++)
#pragma unroll
        for (int nf = 0; nf < 8; nf++)
#pragma unroll
            for (int q = 0; q < 4; q++) acc[mt][nf][q] = 0.f;

    fill_stage(sb,         fA,          fB);          CP_COMMIT();
    fill_stage(sb + STAGE, fA + 2 * KC, fB + 2 * KC); CP_COMMIT();
    const char* pA = fA + 4 * KC;
    const char* pB = fB + 4 * KC;

    uint32_t stC = sb;
    uint32_t stF = sb + 2 * STAGE;
    const uint32_t stEnd = sb + 3 * STAGE;

#pragma unroll 1
    for (int c = 0; c < C; ++c) {
        CP_WAIT1();
        __syncthreads();
        if (c + 2 < C) {
            fill_stage(stF, pA, pB);
            pA += 2 * KC; pB += 2 * KC;
        }
        CP_COMMIT();
#pragma unroll
        for (int ks = 0; ks < 4; ks++) {
            uint32_t kx = (uint32_t)ks << 5;
            uint32_t a[4][4], bh[4][4];
#pragma unroll
            for (int mt = 0; mt < 4; mt++)
                ldsm4(a[mt][0], a[mt][1], a[mt][2], a[mt][3],
                      (stC + arel[mt]) ^ kx);
#pragma unroll
            for (int nt = 0; nt < 4; nt++)
                ldsm4(bh[nt][0], bh[nt][1], bh[nt][2], bh[nt][3],
                      (stC + brel[nt]) ^ kx);
#pragma unroll
            for (int mt = 0; mt < 4; mt++)
#pragma unroll
                for (int nt = 0; nt < 4; nt++) {
                    mma16816(acc[mt][nt * 2],     a[mt], bh[nt][0], bh[nt][2]);
                    mma16816(acc[mt][nt * 2 + 1], a[mt], bh[nt][1], bh[nt][3]);
                }
        }
        stC += STAGE; if (stC == stEnd) stC = sb;
        stF += STAGE; if (stF == stEnd) stF = sb;
    }

    // ---- epilogue ----
    int colb = (lane & 3) * 2;
#pragma unroll
    for (int mt = 0; mt < 4; mt++) {
        int rA = row0 + wm * 64 + mt * 16 + (lane >> 2);
        int rB = rA + 8;
        int tokA = 0, tokB = 0;
        if (MODE == 2) { tokA = g_perm[rA]; tokB = g_perm[rB]; }
#pragma unroll
        for (int nf = 0; nf < 8; nf++) {
            int col = n0 + wn * 64 + nf * 8 + colb;
            float bi0 = bias[(size_t)e * NT + col];
            float bi1 = bias[(size_t)e * NT + col + 1];
            float vA0 = acc[mt][nf][0] + bi0, vA1 = acc[mt][nf][1] + bi1;
            float vB0 = acc[mt][nf][2] + bi0, vB1 = acc[mt][nf][3] + bi1;
            if (MODE == 1) {
                __half2 hA, hB;
                hA.x = __float2half(gelu_exact(vA0));
                hA.y = __float2half(gelu_exact(vA1));
                hB.x = __float2half(gelu_exact(vB0));
                hB.y = __float2half(gelu_exact(vB1));
                *reinterpret_cast<__half2*>(g_H + (size_t)rA * DFF + col) = hA;
                *reinterpret_cast<__half2*>(g_H + (size_t)rB * DFF + col) = hB;
            } else {
                if (tokA < TOK)
                    *reinterpret_cast<float2*>(out + (size_t)tokA * DIM + col) =
                        make_float2(vA0, vA1);
                if (tokB < TOK)
                    *reinterpret_cast<float2*>(out + (size_t)tokB * DIM + col) =
                        make_float2(vB0, vB1);
            }
        }
    }
}

// ---------------- launch (single stream; no events — graph-capture safe) ----
extern "C" void kernel_launch(void* const* d_in, const int* in_sizes, int n_in,
                              void* d_out, int out_size)
{
    const float* x     = (const float*)d_in[0];
    const float* noise = (const float*)d_in[1];
    const float* rw    = (const float*)d_in[2];
    const float* rb    = (const float*)d_in[3];
    const float* w1    = (const float*)d_in[4];
    const float* b1    = (const float*)d_in[5];
    const float* w2    = (const float*)d_in[6];
    const float* b2    = (const float*)d_in[7];
    float* out = (float*)d_out;

    static __half *p_W1, *p_W2, *p_Ag, *p_H;
    static bool resolved = false;
    if (!resolved) {
        cudaGetSymbolAddress((void**)&p_W1, g_W1);
        cudaGetSymbolAddress((void**)&p_W2, g_W2);
        cudaGetSymbolAddress((void**)&p_Ag, g_Ag);
        cudaGetSymbolAddress((void**)&p_H, g_H);
        cudaFuncSetAttribute(gemm_kernel<DIM, DFF, 1>,
                             cudaFuncAttributeMaxDynamicSharedMemorySize, SMEM_REQ);
        cudaFuncSetAttribute(gemm_kernel<DFF, DIM, 2>,
                             cudaFuncAttributeMaxDynamicSharedMemorySize, SMEM_REQ);
        resolved = true;
    }

    // 1: router + W1 convert + W2 convert (one fat, small-smem launch)
    prep_kernel<<<NB_ROUT + 2 * NB_CVT, 256>>>(x, noise, rw, rb,
                                               w1, p_W1, w2, p_W2);
    // 2: full routing resolution in one block
    route_kernel<<<1, 1024>>>();
    // 3: gather + zero-dropped
    gather_kernel<<<PADMAX + TOK / 256, 256>>>(x, out);

    // 4: FFN pass 1: H = gelu(Xg @ W1^T + b1)   K=1024, N=4096 (16 n-tiles)
    gemm_kernel<DIM, DFF, 1><<<dim3(DFF / 256, MAXROWTILES), 256, SMEM_REQ>>>(
        p_Ag, p_W1, b1, nullptr);

    // 5: FFN pass 2: out = H @ W2^T + b2 (scatter)  K=4096, N=1024 (4 n-tiles)
    gemm_kernel<DFF, DIM, 2><<<dim3(DIM / 256, MAXROWTILES), 256, SMEM_REQ>>>(
        p_H, p_W2, b2, out);
}

// round 15
// speedup vs baseline: 1.0907x; 1.0907x over previous
#include <cuda_runtime.h>
#include <cuda_fp16.h>
#include <math.h>
#include <stdint.h>

// ---------------- problem constants ----------------
#define TOK   16384
#define DIM   1024
#define DFF   4096
#define NEXP  8
#define CAP   3277
#define TM    128
#define PADMAX (TOK + NEXP*TM)          // 17408
#define MAXROWTILES (PADMAX/TM)         // 136
#define KC    64                         // K chunk (fp16 elems)
#define STAGE 32768                      // A 16K + B 16K
#define NSTAGE 3
#define SMEM_REQ (NSTAGE*STAGE + 1024)   // 99328; x2 CTAs = 198656 <= 227KB
#define NB_ROUT (TOK/8)                  // 2048 router blocks (8 warps = 8 tokens)
#define NB_CVT  2048                     // blocks per weight tensor (16 tiles each)

// ---------------- device scratch ----------------
__device__ unsigned char g_selmask[TOK];
__device__ signed char   g_final[TOK];
__device__ int g_off[NEXP + 1];
__device__ int g_perm[PADMAX];
__device__ __half g_Ag[(size_t)PADMAX * DIM];        // gathered x, fp16
__device__ __half g_H [(size_t)PADMAX * DFF];        // gelu intermediate, fp16
__device__ __half g_W1[(size_t)NEXP * DFF * DIM];    // W1^T fp16
__device__ __half g_W2[(size_t)NEXP * DIM * DFF];    // W2^T fp16

// ---------------- helpers ----------------
__device__ __forceinline__ uint32_t smem_u32(const void* p) {
    return (uint32_t)__cvta_generic_to_shared(p);
}
#define SWZ128(o) ((o) ^ (((o) >> 3) & 0x70))

#define CP16I(dst, src, DOF, SOF) \
    asm volatile("cp.async.cg.shared.global [%0+%2], [%1+%3], 16;" \
        :: "r"(dst), "l"(src), "n"(DOF), "n"(SOF) : "memory")
#define CP_COMMIT() asm volatile("cp.async.commit_group;" ::: "memory")
#define CP_WAIT1()  asm volatile("cp.async.wait_group 1;" ::: "memory")

__device__ __forceinline__ void ldsm4(uint32_t& r0, uint32_t& r1, uint32_t& r2,
                                      uint32_t& r3, uint32_t addr) {
    asm volatile("ldmatrix.sync.aligned.m8n8.x4.shared.b16 {%0,%1,%2,%3}, [%4];"
                 : "=r"(r0), "=r"(r1), "=r"(r2), "=r"(r3) : "r"(addr));
}

__device__ __forceinline__ void mma16816(float* c, const uint32_t* a,
                                         uint32_t b0, uint32_t b1) {
    asm volatile(
        "mma.sync.aligned.m16n8k16.row.col.f32.f16.f16.f32 "
        "{%0,%1,%2,%3}, {%4,%5,%6,%7}, {%8,%9}, {%0,%1,%2,%3};"
        : "+f"(c[0]), "+f"(c[1]), "+f"(c[2]), "+f"(c[3])
        : "r"(a[0]), "r"(a[1]), "r"(a[2]), "r"(a[3]), "r"(b0), "r"(b1));
}

__device__ __forceinline__ float gelu_exact(float v) {
    return 0.5f * v * (1.0f + erff(v * 0.70710678118654752f));
}

// transpose+convert one 32x32 tile (256 threads, 32x33 smem scratch)
__device__ __forceinline__ void cvt_tile(const float* __restrict__ s,
                                         __half* __restrict__ d,
                                         float* tsh, int R, int C,
                                         int r0, int c0, int tx, int ty)
{
#pragma unroll
    for (int i = 0; i < 4; i++)
        tsh[(ty + i * 8) * 33 + tx] = s[(size_t)(r0 + ty + i * 8) * C + c0 + tx];
    __syncthreads();
#pragma unroll
    for (int i = 0; i < 4; i++) {
        int orow = c0 + ty + i * 8;
        int ocol = r0 + tx;
        d[(size_t)orow * R + ocol] = __float2half(tsh[tx * 33 + ty + i * 8]);
    }
    __syncthreads();
}

// ---------------- prep: router + both weight conversions, one launch -------
__global__ __launch_bounds__(256) void prep_kernel(
    const float* __restrict__ x, const float* __restrict__ noise,
    const float* __restrict__ rw, const float* __restrict__ rb,
    const float* __restrict__ w1, __half* __restrict__ w1dst,
    const float* __restrict__ w2, __half* __restrict__ w2dst)
{
    __shared__ float sh[32 * 33];
    int bid = blockIdx.x;
    int tid = threadIdx.x;

    if (bid < NB_ROUT) {
        int wid = tid >> 5, lane = tid & 31;
        int t = bid * 8 + wid;
        const float4* xr4 = reinterpret_cast<const float4*>(x + (size_t)t * DIM);
        const float4* rw4 = reinterpret_cast<const float4*>(rw);
        float acc[NEXP];
#pragma unroll
        for (int e = 0; e < NEXP; e++) acc[e] = 0.f;
#pragma unroll
        for (int i = 0; i < 8; i++) {
            int idx = i * 32 + lane;
            float4 xv = xr4[idx];
#pragma unroll
            for (int e = 0; e < NEXP; e++) {
                float4 wv = rw4[e * 256 + idx];
                acc[e] += xv.x * wv.x + xv.y * wv.y + xv.z * wv.z + xv.w * wv.w;
            }
        }
#pragma unroll
        for (int o = 16; o > 0; o >>= 1)
#pragma unroll
            for (int e = 0; e < NEXP; e++)
                acc[e] += __shfl_xor_sync(0xFFFFFFFFu, acc[e], o);
        if (lane == 0) {
            float lg[NEXP];
#pragma unroll
            for (int e = 0; e < NEXP; e++)
                lg[e] = acc[e] + rb[e] + noise[t * NEXP + e] * 0.02f;
            int e1 = 0;
#pragma unroll
            for (int e = 1; e < NEXP; e++) if (lg[e] > lg[e1]) e1 = e;
            int e2 = -1;
#pragma unroll
            for (int e = 0; e < NEXP; e++) {
                if (e == e1) continue;
                if (e2 < 0 || lg[e] > lg[e2]) e2 = e;
            }
            g_selmask[t] = (unsigned char)((1 << e1) | (1 << e2));
        }
        return;
    }

    int tx = tid & 31, ty = tid >> 5;
    if (bid < NB_ROUT + NB_CVT) {
        int cb = bid - NB_ROUT;
#pragma unroll 1
        for (int it = 0; it < 16; it++) {
            int g = cb * 16 + it;
            int e = g >> 12;
            int rem = g & 4095;
            int tr = rem & 31;
            int tc = rem >> 5;
            cvt_tile(w1 + (size_t)e * DIM * DFF, w1dst + (size_t)e * DFF * DIM,
                     sh, DIM, DFF, tr * 32, tc * 32, tx, ty);
        }
        return;
    }
    int cb = bid - NB_ROUT - NB_CVT;
#pragma unroll 1
    for (int it = 0; it < 16; it++) {
        int g = cb * 16 + it;
        int e = g >> 12;
        int rem = g & 4095;
        int tr = rem & 127;
        int tc = rem >> 7;
        cvt_tile(w2 + (size_t)e * DFF * DIM, w2dst + (size_t)e * DIM * DFF,
                 sh, DFF, DIM, tr * 32, tc * 32, tx, ty);
    }
}

// ---------------- route: full routing resolution in one block --------------
__global__ __launch_bounds__(1024) void route_kernel()
{
    __shared__ uint64_t s0[1024], s1[1024];
    __shared__ int sF[NEXP], sOff[NEXP + 1];
    int tid = threadIdx.x;

    union { uint4 q; unsigned char b[16]; } u;
    u.q = reinterpret_cast<const uint4*>(g_selmask)[tid];
    uint32_t m[NEXP];
#pragma unroll
    for (int e = 0; e < NEXP; e++) m[e] = 0;
#pragma unroll
    for (int j = 0; j < 16; j++) {
        unsigned char sm = u.b[j];
#pragma unroll
        for (int e = 0; e < NEXP; e++)
            m[e] |= (uint32_t)((sm >> e) & 1) << j;
    }
    int cnt[NEXP];
#pragma unroll
    for (int e = 0; e < NEXP; e++) cnt[e] = __popc(m[e]);

    uint64_t p0 = (uint64_t)cnt[0] | ((uint64_t)cnt[1] << 16) |
                  ((uint64_t)cnt[2] << 32) | ((uint64_t)cnt[3] << 48);
    uint64_t p1 = (uint64_t)cnt[4] | ((uint64_t)cnt[5] << 16) |
                  ((uint64_t)cnt[6] << 32) | ((uint64_t)cnt[7] << 48);
    s0[tid] = p0; s1[tid] = p1;
    __syncthreads();
    for (int off = 1; off < 1024; off <<= 1) {
        uint64_t a0 = (tid >= off) ? s0[tid - off] : 0;
        uint64_t a1 = (tid >= off) ? s1[tid - off] : 0;
        __syncthreads();
        s0[tid] += a0; s1[tid] += a1;
        __syncthreads();
    }
    uint64_t i0 = s0[tid], i1 = s1[tid];
    int base[NEXP];
#pragma unroll
    for (int e = 0; e < 4; e++)
        base[e] = (int)((i0 >> (16 * e)) & 0xFFFF) - cnt[e];
#pragma unroll
    for (int e = 4; e < NEXP; e++)
        base[e] = (int)((i1 >> (16 * (e - 4))) & 0xFFFF) - cnt[e];

    union { int4 q; signed char c[16]; } fo;
    uint32_t fm[NEXP];
#pragma unroll
    for (int e = 0; e < NEXP; e++) fm[e] = 0;
#pragma unroll
    for (int j = 0; j < 16; j++) {
        int f = -1;
#pragma unroll
        for (int e = NEXP - 1; e >= 0; e--) {
            if ((m[e] >> j) & 1) {
                int rank = base[e] + __popc(m[e] & ((1u << j) - 1u));
                if (rank < CAP) { f = e; break; }
            }
        }
        fo.c[j] = (signed char)f;
        if (f >= 0) fm[f] |= 1u << j;
    }
    reinterpret_cast<int4*>(g_final)[tid] = fo.q;

    int fc[NEXP];
#pragma unroll
    for (int e = 0; e < NEXP; e++) fc[e] = __popc(fm[e]);
    uint64_t q0 = (uint64_t)fc[0] | ((uint64_t)fc[1] << 16) |
                  ((uint64_t)fc[2] << 32) | ((uint64_t)fc[3] << 48);
    uint64_t q1 = (uint64_t)fc[4] | ((uint64_t)fc[5] << 16) |
                  ((uint64_t)fc[6] << 32) | ((uint64_t)fc[7] << 48);
    __syncthreads();
    s0[tid] = q0; s1[tid] = q1;
    __syncthreads();
    for (int off = 1; off < 1024; off <<= 1) {
        uint64_t a0 = (tid >= off) ? s0[tid - off] : 0;
        uint64_t a1 = (tid >= off) ? s1[tid - off] : 0;
        __syncthreads();
        s0[tid] += a0; s1[tid] += a1;
        __syncthreads();
    }
    uint64_t j0 = s0[tid], j1 = s1[tid];
    int fbase[NEXP];
#pragma unroll
    for (int e = 0; e < 4; e++)
        fbase[e] = (int)((j0 >> (16 * e)) & 0xFFFF) - fc[e];
#pragma unroll
    for (int e = 4; e < NEXP; e++)
        fbase[e] = (int)((j1 >> (16 * (e - 4))) & 0xFFFF) - fc[e];

    if (tid == 1023) {
        int o = 0;
        sOff[0] = 0;
        for (int e = 0; e < NEXP; e++) {
            int F = (e < 4) ? (int)((j0 >> (16 * e)) & 0xFFFF)
                            : (int)((j1 >> (16 * (e - 4))) & 0xFFFF);
            sF[e] = F;
            o += ((F + TM - 1) / TM) * TM;
            sOff[e + 1] = o;
        }
    }
    __syncthreads();
    if (tid <= NEXP) g_off[tid] = sOff[tid];

#pragma unroll
    for (int j = 0; j < 16; j++) {
        int f = fo.c[j];
        if (f >= 0) {
            int pos = sOff[f] + fbase[f] + __popc(fm[f] & ((1u << j) - 1u));
            g_perm[pos] = tid * 16 + j;
        }
    }
    for (int e = 0; e < NEXP; e++)
        for (int i = sOff[e] + sF[e] + tid; i < sOff[e + 1]; i += 1024)
            g_perm[i] = TOK;
}

// fat gather: gather + zero-dropped
__global__ __launch_bounds__(256) void gather_kernel(
    const float* __restrict__ x, float* __restrict__ out)
{
    int bid = blockIdx.x;
    int tid = threadIdx.x;
    if (bid < PADMAX) {
        int tok = g_perm[bid];
        float4 v = make_float4(0.f, 0.f, 0.f, 0.f);
        if (tok < TOK)
            v = reinterpret_cast<const float4*>(x + (size_t)tok * DIM)[tid];
        __half h[4];
        h[0] = __float2half(v.x); h[1] = __float2half(v.y);
        h[2] = __float2half(v.z); h[3] = __float2half(v.w);
        reinterpret_cast<uint2*>(g_Ag + (size_t)bid * DIM)[tid] =
            *reinterpret_cast<uint2*>(h);
        return;
    }
    __shared__ int list[256];
    __shared__ int cnt;
    if (tid == 0) cnt = 0;
    __syncthreads();
    int t = (bid - PADMAX) * 256 + tid;
    if (g_final[t] < 0) { int p = atomicAdd(&cnt, 1); list[p] = t; }
    __syncthreads();
    float4 z = make_float4(0.f, 0.f, 0.f, 0.f);
    for (int i = 0; i < cnt; i++) {
        size_t row = (size_t)list[i] * DIM;
        reinterpret_cast<float4*>(out + row)[tid] = z;
    }
}

// ---------------- HMMA GEMM — R13 shape + k=32 macro-step inner loop -------
// 128x128 CTA tile, 8 warps (4m x 2n) of 32x64, 2 CTAs/SM, 3-stage cp.async.
// Inner loop: 2 macro-steps per chunk, each = 12 ldsm then 32 MMAs
// (double the MMA run per ldsm dependency window vs R13).
template<int KT, int NT, int MODE>
__global__ __launch_bounds__(256, 2) void gemm_kernel(
    const __half* __restrict__ A, const __half* __restrict__ B,
    const float* __restrict__ bias, float* __restrict__ out)
{
    int row0 = blockIdx.y * TM;
    if (row0 >= g_off[NEXP]) return;
    int e = 0;
#pragma unroll
    for (int i = 0; i < NEXP; i++) if (row0 >= g_off[i + 1]) e = i + 1;
    int n0 = blockIdx.x * 128;

    extern __shared__ __align__(1024) char smem_raw[];
    uint32_t sb = (smem_u32(smem_raw) + 1023) & ~1023u;

    int tid = threadIdx.x;
    int lane = tid & 31;
    int wid = tid >> 5;
    int wm = wid & 3;
    int wn = wid >> 2;
    int lrow = (lane & 7) + ((lane >> 3) & 1) * 8;
    int lkh2 = ((lane >> 4) * 8) * 2;

    constexpr int C = KT >> 6;

    uint32_t so = SWZ128(((tid >> 3) << 7) + ((tid & 7) << 4));
    const char* fA = (const char*)(A + (size_t)(row0 + (tid >> 3)) * KT
                                     + (tid & 7) * 8);
    const char* fB = (const char*)(B + ((size_t)e * NT + n0 + (tid >> 3)) * KT
                                     + (tid & 7) * 8);

    auto fill_stage = [&](uint32_t st, const char* a, const char* b) {
        uint32_t dA = st + so, dB = st + 16384 + so;
        CP16I(dA, a,     0, 0);
        CP16I(dA, a,  4096, 64 * KT);
        CP16I(dA, a,  8192, 128 * KT);
        CP16I(dA, a, 12288, 192 * KT);
        CP16I(dB, b,     0, 0);
        CP16I(dB, b,  4096, 64 * KT);
        CP16I(dB, b,  8192, 128 * KT);
        CP16I(dB, b, 12288, 192 * KT);
    };

    uint32_t arel[2], brel[4];
#pragma unroll
    for (int mt = 0; mt < 2; mt++)
        arel[mt] = SWZ128(((wm * 32 + mt * 16 + lrow) << 7) + lkh2);
#pragma unroll
    for (int nt = 0; nt < 4; nt++)
        brel[nt] = 16384u + SWZ128(((wn * 64 + nt * 16 + lrow) << 7) + lkh2);

    float acc[2][8][4];
#pragma unroll
    for (int mt = 0; mt < 2; mt++)
#pragma unroll
        for (int nf = 0; nf < 8; nf++)
#pragma unroll
            for (int q = 0; q < 4; q++) acc[mt][nf][q] = 0.f;

    fill_stage(sb,         fA,          fB);          CP_COMMIT();
    fill_stage(sb + STAGE, fA + 2 * KC, fB + 2 * KC); CP_COMMIT();
    const char* pA = fA + 4 * KC;
    const char* pB = fB + 4 * KC;

    uint32_t stC = sb;
    uint32_t stF = sb + 2 * STAGE;
    const uint32_t stEnd = sb + 3 * STAGE;

#pragma unroll 1
    for (int c = 0; c < C; ++c) {
        CP_WAIT1();
        __syncthreads();
        if (c + 2 < C) {
            fill_stage(stF, pA, pB);
            pA += 2 * KC; pB += 2 * KC;
        }
        CP_COMMIT();
        uint32_t ab0 = stC + arel[0], ab1 = stC + arel[1];
        uint32_t bb0 = stC + brel[0], bb1 = stC + brel[1];
        uint32_t bb2 = stC + brel[2], bb3 = stC + brel[3];
#pragma unroll
        for (int kq = 0; kq < 2; kq++) {          // k=32 macro-steps
            uint32_t kx0 = (uint32_t)kq << 6;     // 0, 64
            uint32_t kx1 = kx0 | 32u;
            uint32_t a[2][2][4], bh[2][4][4];
            // issue all 12 ldsm first
            ldsm4(a[0][0][0], a[0][0][1], a[0][0][2], a[0][0][3], ab0 ^ kx0);
            ldsm4(a[0][1][0], a[0][1][1], a[0][1][2], a[0][1][3], ab1 ^ kx0);
            ldsm4(a[1][0][0], a[1][0][1], a[1][0][2], a[1][0][3], ab0 ^ kx1);
            ldsm4(a[1][1][0], a[1][1][1], a[1][1][2], a[1][1][3], ab1 ^ kx1);
            ldsm4(bh[0][0][0], bh[0][0][1], bh[0][0][2], bh[0][0][3], bb0 ^ kx0);
            ldsm4(bh[0][1][0], bh[0][1][1], bh[0][1][2], bh[0][1][3], bb1 ^ kx0);
            ldsm4(bh[0][2][0], bh[0][2][1], bh[0][2][2], bh[0][2][3], bb2 ^ kx0);
            ldsm4(bh[0][3][0], bh[0][3][1], bh[0][3][2], bh[0][3][3], bb3 ^ kx0);
            ldsm4(bh[1][0][0], bh[1][0][1], bh[1][0][2], bh[1][0][3], bb0 ^ kx1);
            ldsm4(bh[1][1][0], bh[1][1][1], bh[1][1][2], bh[1][1][3], bb1 ^ kx1);
            ldsm4(bh[1][2][0], bh[1][2][1], bh[1][2][2], bh[1][2][3], bb2 ^ kx1);
            ldsm4(bh[1][3][0], bh[1][3][1], bh[1][3][2], bh[1][3][3], bb3 ^ kx1);
            // then 64 MMAs
#pragma unroll
            for (int s = 0; s < 2; s++)
#pragma unroll
                for (int mt = 0; mt < 2; mt++)
#pragma unroll
                    for (int nt = 0; nt < 4; nt++) {
                        mma16816(acc[mt][nt * 2],     a[s][mt],
                                 bh[s][nt][0], bh[s][nt][2]);
                        mma16816(acc[mt][nt * 2 + 1], a[s][mt],
                                 bh[s][nt][1], bh[s][nt][3]);
                    }
        }
        stC += STAGE; if (stC == stEnd) stC = sb;
        stF += STAGE; if (stF == stEnd) stF = sb;
    }

    // ---- epilogue ----
    int colb = (lane & 3) * 2;
#pragma unroll
    for (int mt = 0; mt < 2; mt++) {
        int rA = row0 + wm * 32 + mt * 16 + (lane >> 2);
        int rB = rA + 8;
        int tokA = 0, tokB = 0;
        if (MODE == 2) { tokA = g_perm[rA]; tokB = g_perm[rB]; }
#pragma unroll
        for (int nf = 0; nf < 8; nf++) {
            int col = n0 + wn * 64 + nf * 8 + colb;
            float bi0 = bias[(size_t)e * NT + col];
            float bi1 = bias[(size_t)e * NT + col + 1];
            float vA0 = acc[mt][nf][0] + bi0, vA1 = acc[mt][nf][1] + bi1;
            float vB0 = acc[mt][nf][2] + bi0, vB1 = acc[mt][nf][3] + bi1;
            if (MODE == 1) {
                __half2 hA, hB;
                hA.x = __float2half(gelu_exact(vA0));
                hA.y = __float2half(gelu_exact(vA1));
                hB.x = __float2half(gelu_exact(vB0));
                hB.y = __float2half(gelu_exact(vB1));
                *reinterpret_cast<__half2*>(g_H + (size_t)rA * DFF + col) = hA;
                *reinterpret_cast<__half2*>(g_H + (size_t)rB * DFF + col) = hB;
            } else {
                if (tokA < TOK)
                    *reinterpret_cast<float2*>(out + (size_t)tokA * DIM + col) =
                        make_float2(vA0, vA1);
                if (tokB < TOK)
                    *reinterpret_cast<float2*>(out + (size_t)tokB * DIM + col) =
                        make_float2(vB0, vB1);
            }
        }
    }
}

// ---------------- launch (single stream; no events — graph-capture safe) ----
extern "C" void kernel_launch(void* const* d_in, const int* in_sizes, int n_in,
                              void* d_out, int out_size)
{
    const float* x     = (const float*)d_in[0];
    const float* noise = (const float*)d_in[1];
    const float* rw    = (const float*)d_in[2];
    const float* rb    = (const float*)d_in[3];
    const float* w1    = (const float*)d_in[4];
    const float* b1    = (const float*)d_in[5];
    const float* w2    = (const float*)d_in[6];
    const float* b2    = (const float*)d_in[7];
    float* out = (float*)d_out;

    static __half *p_W1, *p_W2, *p_Ag, *p_H;
    static bool resolved = false;
    if (!resolved) {
        cudaGetSymbolAddress((void**)&p_W1, g_W1);
        cudaGetSymbolAddress((void**)&p_W2, g_W2);
        cudaGetSymbolAddress((void**)&p_Ag, g_Ag);
        cudaGetSymbolAddress((void**)&p_H, g_H);
        cudaFuncSetAttribute(gemm_kernel<DIM, DFF, 1>,
                             cudaFuncAttributeMaxDynamicSharedMemorySize, SMEM_REQ);
        cudaFuncSetAttribute(gemm_kernel<DFF, DIM, 2>,
                             cudaFuncAttributeMaxDynamicSharedMemorySize, SMEM_REQ);
        resolved = true;
    }

    // 1: router + W1 convert + W2 convert (one fat, small-smem launch)
    prep_kernel<<<NB_ROUT + 2 * NB_CVT, 256>>>(x, noise, rw, rb,
                                               w1, p_W1, w2, p_W2);
    // 2: full routing resolution in one block
    route_kernel<<<1, 1024>>>();
    // 3: gather + zero-dropped
    gather_kernel<<<PADMAX + TOK / 256, 256>>>(x, out);

    // 4: FFN pass 1: H = gelu(Xg @ W1^T + b1)   K=1024, N=4096
    gemm_kernel<DIM, DFF, 1><<<dim3(DFF / 128, MAXROWTILES), 256, SMEM_REQ>>>(
        p_Ag, p_W1, b1, nullptr);

    // 5: FFN pass 2: out = H @ W2^T + b2 (scatter)   K=4096, N=1024
    gemm_kernel<DFF, DIM, 2><<<dim3(DIM / 128, MAXROWTILES), 256, SMEM_REQ>>>(
        p_H, p_W2, b2, out);
}